// round 11
// baseline (speedup 1.0000x reference)
#include <cuda_runtime.h>
#include <cuda_fp16.h>
#include <math.h>
#include <stdint.h>
#include <mma.h>

using namespace nvcuda;

// Problem constants
#define B    64
#define T    2048
#define ENC  512
#define DEC  512
#define ATTN 256

// Energy GEMM tiling (64-row tiles)
#define TILE_M  64
#define KC      64
#define NCHUNK  (ENC / KC)         // 8

#define A_LD_H  72
#define B_LD_H  264
#define C_LDH   264                // half-tile leading dim (halves)
#define CTILE_H (TILE_M * C_LDH)   // halves per C tile

#define A_SLOT_B (TILE_M * A_LD_H * 2)      // 9216, 2 slots
#define B_SLOT_B (KC * B_LD_H * 2)          // 33792, 2 slots
#define META_B   2048
#define A0_OFF   META_B
#define B0_OFF   (META_B + 2 * A_SLOT_B)
#define DYN_SMEM (B0_OFF + 2 * B_SLOT_B)    // 88064
// epilogue: 2 half C tiles = 2*64*264*2 = 67584 B at META_B (fits)

// Context split-T (fused softmax)
#define CSEG     32
#define CT       (T / CSEG)        // 64

// ---- scratch (no allocations allowed) ----
__device__ __half g_enc_h[(size_t)B * T * ENC];   // 128 MB
__device__ __half g_We_h[ENC * ATTN];
__device__ float  g_proj_dec[B * ATTN];
__device__ float  g_energy[B * T];
__device__ float  g_ctx_part[CSEG * B * ENC];     // 4 MB
__device__ int    g_mask_is_byte;

// ---------------------------------------------------------------------------
__device__ __forceinline__ uint32_t smem_u32(const void* p) {
    uint32_t a;
    asm("{ .reg .u64 t; cvta.to.shared.u64 t, %1; cvt.u32.u64 %0, t; }" : "=r"(a) : "l"(p));
    return a;
}
__device__ __forceinline__ float fast_tanh(float x) {
    float y; asm("tanh.approx.f32 %0, %1;" : "=f"(y) : "f"(x)); return y;
}
__device__ __forceinline__ void cp_async16(uint32_t s, const void* g) {
    asm volatile("cp.async.cg.shared.global [%0], [%1], 16;" :: "r"(s), "l"(g));
}
#define CP_COMMIT() asm volatile("cp.async.commit_group;" ::: "memory")
#define CP_WAIT(n)  asm volatile("cp.async.wait_group %0;" :: "n"(n) : "memory")

// ---------------------------------------------------------------------------
// Fused prologue: projdec (0-255), convert_we (256-287), mask detect (288).
// ---------------------------------------------------------------------------
__global__ void __launch_bounds__(256)
prep_kernel(const float* __restrict__ dec, const float* __restrict__ Wd,
            const float* __restrict__ We, const unsigned char* __restrict__ mask) {
    const int blk = blockIdx.x, tid = threadIdx.x;

    if (blk < 256) {
        __shared__ float sd[DEC];
        __shared__ float sp[256];
        const int b = blk >> 2, q = blk & 3;
        const int a = q * 64 + (tid & 63);
        const int kseg = tid >> 6;
        sd[tid]       = dec[b * DEC + tid];
        sd[tid + 256] = dec[b * DEC + tid + 256];
        __syncthreads();
        const float* wp = Wd + (size_t)(kseg * 128) * ATTN + a;
        const float* dp = sd + kseg * 128;
        float a0 = 0.f, a1 = 0.f, a2 = 0.f, a3 = 0.f;
        #pragma unroll 8
        for (int i = 0; i < 128; i += 4) {
            a0 = fmaf(dp[i + 0], wp[(size_t)(i + 0) * ATTN], a0);
            a1 = fmaf(dp[i + 1], wp[(size_t)(i + 1) * ATTN], a1);
            a2 = fmaf(dp[i + 2], wp[(size_t)(i + 2) * ATTN], a2);
            a3 = fmaf(dp[i + 3], wp[(size_t)(i + 3) * ATTN], a3);
        }
        sp[tid] = (a0 + a1) + (a2 + a3);
        __syncthreads();
        if (tid < 64)
            g_proj_dec[b * ATTN + q * 64 + tid] =
                sp[tid] + sp[tid + 64] + sp[tid + 128] + sp[tid + 192];
    } else if (blk < 288) {
        const int blk2 = blk - 256;
        const float4* in = (const float4*)We;
        uint2* out = (uint2*)g_We_h;
        #pragma unroll
        for (int j = 0; j < 4; j++) {
            int i = blk2 * 256 + tid + j * 8192;
            float4 x = in[i];
            union { uint2 u; __half2 h[2]; } cv;
            cv.h[0] = __floats2half2_rn(x.x, x.y);
            cv.h[1] = __floats2half2_rn(x.z, x.w);
            out[i] = cv.u;
        }
    } else {
        __shared__ int f;
        if (tid == 0) f = 0;
        __syncthreads();
        const uint4* m4 = (const uint4*)mask;
        uint32_t acc = 0;
        #pragma unroll 8
        for (int j = 0; j < 32; j++) {
            uint4 w = m4[tid + j * 256];
            acc |= (w.x | w.y | w.z | w.w) & 0xFFFFFF00u;
        }
        if (acc) atomicOr(&f, 1);
        __syncthreads();
        if (tid == 0) g_mask_is_byte = f;
    }
}

// ---------------------------------------------------------------------------
// Fused energy kernel: fp16 WMMA 64x256x512 with fp16 accumulators in two
// K=256 sets (promoted to f32 in epilogue). grid (T/64, B), block 256.
// ---------------------------------------------------------------------------
__device__ __forceinline__ void ldg_a(const float* __restrict__ enc_tile,
                                      int c, float4* r, int tid) {
    const float* p = enc_tile + c * KC;
    #pragma unroll
    for (int it = 0; it < 4; it++) {
        int idx = it * 256 + tid;
        int row = idx >> 4, col4 = idx & 15;
        r[it] = *(const float4*)(p + (size_t)row * ENC + col4 * 4);
    }
}

__device__ __forceinline__ void cvt_sts_a(const float4* r, int c, __half* aslot,
                                          __half* __restrict__ gdst_tile, int tid) {
    #pragma unroll
    for (int it = 0; it < 4; it++) {
        int idx = it * 256 + tid;
        int row = idx >> 4, col4 = idx & 15;
        union { uint2 u; __half2 h[2]; } cv;
        cv.h[0] = __floats2half2_rn(r[it].x, r[it].y);
        cv.h[1] = __floats2half2_rn(r[it].z, r[it].w);
        *(uint2*)(aslot + row * A_LD_H + col4 * 4) = cv.u;
        *(uint2*)(gdst_tile + (size_t)row * ENC + c * KC + col4 * 4) = cv.u;
    }
}

__device__ __forceinline__ void load_b(int c, uint32_t bslot_u, int tid) {
    const __half* bsrc = g_We_h + (size_t)c * KC * ATTN;
    #pragma unroll
    for (int it = 0; it < 8; it++) {
        int idx = it * 256 + tid;
        int row = idx >> 5, seg = idx & 31;
        cp_async16(bslot_u + (uint32_t)(row * B_LD_H + seg * 8) * 2,
                   bsrc + (size_t)row * ATTN + seg * 8);
    }
}

__global__ void __launch_bounds__(256, 2)
energy_wmma_kernel(const float* __restrict__ enc, const float* __restrict__ v) {
    extern __shared__ char dsm[];
    float* pd_s = (float*)dsm;
    float* v_s  = (float*)(dsm + ATTN * 4);
    __half* ch_s = (__half*)(dsm + META_B);          // epilogue: 2 half C tiles

    const uint32_t sb = smem_u32(dsm);

    const int tid  = threadIdx.x;
    const int wid  = tid >> 5;
    const int wm   = wid & 1;
    const int wn   = wid >> 1;
    const int b    = blockIdx.y;
    const int t0   = blockIdx.x * TILE_M;
    const float* enc_tile = enc + ((size_t)b * T + t0) * ENC;
    __half* gdst_tile = g_enc_h + ((size_t)b * T + t0) * ENC;

    pd_s[tid] = g_proj_dec[b * ATTN + tid];
    v_s[tid]  = v[tid];

    // two fp16 accumulator sets: set0 = chunks 0..3 (K 0..255), set1 = 4..7
    wmma::fragment<wmma::accumulator, 16, 16, 16, __half> cfh[2][2][4];
    #pragma unroll
    for (int s = 0; s < 2; s++)
        #pragma unroll
        for (int i = 0; i < 2; i++)
            #pragma unroll
            for (int j = 0; j < 4; j++)
                wmma::fill_fragment(cfh[s][i][j], __float2half(0.0f));

    float4 rnext[4];

    ldg_a(enc_tile, 0, rnext, tid);
    load_b(0, sb + B0_OFF, tid);  CP_COMMIT();
    cvt_sts_a(rnext, 0, (__half*)(dsm + A0_OFF), gdst_tile, tid);
    ldg_a(enc_tile, 1, rnext, tid);
    load_b(1, sb + B0_OFF + B_SLOT_B, tid);  CP_COMMIT();
    CP_WAIT(1);
    __syncthreads();

    #pragma unroll 1
    for (int c = 0; c < NCHUNK; c++) {
        if (c + 1 < NCHUNK)
            cvt_sts_a(rnext, c + 1,
                      (__half*)(dsm + A0_OFF + ((c + 1) & 1) * A_SLOT_B),
                      gdst_tile, tid);
        if (c + 2 < NCHUNK)
            ldg_a(enc_tile, c + 2, rnext, tid);

        const int set = c >> 2;
        const __half* a_s = (const __half*)(dsm + A0_OFF + (c & 1) * A_SLOT_B);
        const __half* b_s = (const __half*)(dsm + B0_OFF + (c & 1) * B_SLOT_B);
        #pragma unroll
        for (int ks = 0; ks < KC / 16; ks++) {
            wmma::fragment<wmma::matrix_a, 16, 16, 16, __half, wmma::row_major> af[2];
            #pragma unroll
            for (int i = 0; i < 2; i++)
                wmma::load_matrix_sync(af[i],
                    a_s + (size_t)(wm * 32 + i * 16) * A_LD_H + ks * 16, A_LD_H);
            #pragma unroll
            for (int j = 0; j < 4; j++) {
                wmma::fragment<wmma::matrix_b, 16, 16, 16, __half, wmma::row_major> bfrag;
                wmma::load_matrix_sync(bfrag,
                    b_s + (size_t)(ks * 16) * B_LD_H + wn * 64 + j * 16, B_LD_H);
                #pragma unroll
                for (int i = 0; i < 2; i++)
                    wmma::mma_sync(cfh[set][i][j], af[i], bfrag, cfh[set][i][j]);
            }
        }

        if (c + 1 < NCHUNK) CP_WAIT(0);
        __syncthreads();
        if (c + 2 < NCHUNK) {
            load_b(c + 2, sb + B0_OFF + (c & 1) * B_SLOT_B, tid);
            CP_COMMIT();
        }
    }

    // store both half C tiles (64 x 256, ld 264)
    #pragma unroll
    for (int s = 0; s < 2; s++)
        #pragma unroll
        for (int i = 0; i < 2; i++)
            #pragma unroll
            for (int j = 0; j < 4; j++)
                wmma::store_matrix_sync(
                    ch_s + (size_t)s * CTILE_H
                         + (size_t)(wm * 32 + i * 16) * C_LDH + wn * 64 + j * 16,
                    cfh[s][i][j], C_LDH, wmma::mem_row_major);
    __syncthreads();

    const int row = tid >> 2, q = tid & 3;
    const __half* c0 = ch_s + (size_t)row * C_LDH + q * 64;
    const __half* c1 = c0 + CTILE_H;
    const float* pdq = pd_s + q * 64;
    const float* vq  = v_s + q * 64;
    float e = 0.f;
    #pragma unroll 8
    for (int j = 0; j < 64; j++) {
        float cc = __half2float(c0[j]) + __half2float(c1[j]);
        e = fmaf(fast_tanh(cc + pdq[j]), vq[j], e);
    }
    e += __shfl_xor_sync(0xffffffffu, e, 1);
    e += __shfl_xor_sync(0xffffffffu, e, 2);
    if (q == 0)
        g_energy[b * T + t0 + row] = e;
}

// ---------------------------------------------------------------------------
// Fused softmax + context partials: grid (B, CSEG), block 128.
// ---------------------------------------------------------------------------
__global__ void __launch_bounds__(128)
ctx_softmax_kernel(const void* __restrict__ mask,
                   float* __restrict__ attn_out) {
    __shared__ float sred[8];
    __shared__ float sw[CT];

    const int b   = blockIdx.x;
    const int seg = blockIdx.y;
    const int tb  = seg * CT;
    const int tid = threadIdx.x;

    const bool isbyte = (g_mask_is_byte != 0);
    const unsigned char* mb = (const unsigned char*)mask;
    const int*           mi = (const int*)mask;

    float e[16];
    #pragma unroll
    for (int j = 0; j < 16; j++) {
        const int i = b * T + tid + j * 128;
        const bool m = isbyte ? (mb[i] != 0) : (mi[i] != 0);
        e[j] = m ? -INFINITY : g_energy[i];
    }
    float mx = e[0];
    #pragma unroll
    for (int j = 1; j < 16; j++) mx = fmaxf(mx, e[j]);
    #pragma unroll
    for (int o = 16; o > 0; o >>= 1)
        mx = fmaxf(mx, __shfl_xor_sync(0xffffffffu, mx, o));
    if ((tid & 31) == 0) sred[tid >> 5] = mx;
    __syncthreads();
    if (tid < 32) {
        float t = (tid < 4) ? sred[tid] : -INFINITY;
        #pragma unroll
        for (int o = 2; o > 0; o >>= 1)
            t = fmaxf(t, __shfl_xor_sync(0xffffffffu, t, o));
        if (tid == 0) sred[4] = t;
    }
    __syncthreads();
    mx = sred[4];

    const bool allmasked = !(mx > -INFINITY);

    float s = 0.f;
    #pragma unroll
    for (int j = 0; j < 16; j++)
        s += (allmasked || e[j] == -INFINITY) ? 0.f : expf(e[j] - mx);
    #pragma unroll
    for (int o = 16; o > 0; o >>= 1)
        s += __shfl_xor_sync(0xffffffffu, s, o);
    __syncthreads();
    if ((tid & 31) == 0) sred[tid >> 5] = s;
    __syncthreads();
    if (tid < 32) {
        float t = (tid < 4) ? sred[tid] : 0.f;
        #pragma unroll
        for (int o = 2; o > 0; o >>= 1)
            t += __shfl_xor_sync(0xffffffffu, t, o);
        if (tid == 0) sred[5] = t;
    }
    __syncthreads();
    s = sred[5];
    const float inv = (s > 0.f) ? (1.f / s) : 0.f;

    if (tid < CT) {
        const int i = b * T + tb + tid;
        const bool m = isbyte ? (mb[i] != 0) : (mi[i] != 0);
        const float ev = (allmasked || m) ? -INFINITY : g_energy[i];
        const float w = (ev == -INFINITY) ? 0.f : expf(ev - mx) * inv;
        sw[tid] = w;
        attn_out[i] = w;
    }
    __syncthreads();

    const uint2* ep = (const uint2*)(g_enc_h + ((size_t)b * T + tb) * ENC) + tid;
    float4 acc = {0.f, 0.f, 0.f, 0.f};
    #pragma unroll 8
    for (int t = 0; t < CT; t++) {
        union { uint2 u; __half2 h[2]; } w;
        w.u = ep[(size_t)t * (ENC / 4)];
        const float sc = sw[t];
        float2 f0 = __half22float2(w.h[0]);
        float2 f1 = __half22float2(w.h[1]);
        acc.x = fmaf(sc, f0.x, acc.x);
        acc.y = fmaf(sc, f0.y, acc.y);
        acc.z = fmaf(sc, f1.x, acc.z);
        acc.w = fmaf(sc, f1.y, acc.w);
    }
    *(float4*)(g_ctx_part + ((size_t)seg * B + b) * ENC + tid * 4) = acc;
}

// ---------------------------------------------------------------------------
// context reduce over CSEG partials: grid (B, 4), block 128 (MLP-32/thread)
// ---------------------------------------------------------------------------
__global__ void __launch_bounds__(128)
context_reduce_kernel(float* __restrict__ ctx) {
    const int b = blockIdx.x;
    const int e = blockIdx.y * 128 + threadIdx.x;
    float s = 0.f;
    #pragma unroll
    for (int seg = 0; seg < CSEG; seg++)
        s += g_ctx_part[((size_t)seg * B + b) * ENC + e];
    ctx[b * ENC + e] = s;
}

// ---------------------------------------------------------------------------
extern "C" void kernel_launch(void* const* d_in, const int* in_sizes, int n_in,
                              void* d_out, int out_size) {
    const float* enc  = (const float*)d_in[0];
    const float* dec  = (const float*)d_in[1];
    const void*  mask = d_in[2];
    const float* We   = (const float*)d_in[3];
    const float* Wd   = (const float*)d_in[4];
    const float* v    = (const float*)d_in[5];

    float* out_ctx  = (float*)d_out;
    float* out_attn = out_ctx + B * ENC;

    cudaFuncSetAttribute(energy_wmma_kernel,
                         cudaFuncAttributeMaxDynamicSharedMemorySize, DYN_SMEM);

    prep_kernel<<<289, 256>>>(dec, Wd, We, (const unsigned char*)mask);
    energy_wmma_kernel<<<dim3(T / TILE_M, B), 256, DYN_SMEM>>>(enc, v);
    ctx_softmax_kernel<<<dim3(B, CSEG), 128>>>(mask, out_attn);
    context_reduce_kernel<<<dim3(B, 4), 128>>>(out_ctx);
}

// round 12
// speedup vs baseline: 1.5021x; 1.5021x over previous
#include <cuda_runtime.h>
#include <cuda_fp16.h>
#include <math.h>
#include <stdint.h>
#include <mma.h>

using namespace nvcuda;

// Problem constants
#define B    64
#define T    2048
#define ENC  512
#define DEC  512
#define ATTN 256

// Energy GEMM tiling: 128x256 CTA tile, 8 warps, warp tile 64x64
#define TILE_M  128
#define KC      64
#define NCHUNK  (ENC / KC)         // 8

#define A_LD_H  72
#define B_LD_H  264
#define C_LD    264

#define A_SLOT_B (TILE_M * A_LD_H * 2)      // 18432, 2 slots
#define B_SLOT_B (KC * B_LD_H * 2)          // 33792, 2 slots
#define META_B   2048
#define A0_OFF   META_B
#define B0_OFF   (META_B + 2 * A_SLOT_B)    // 38912
#define PIPE_END (B0_OFF + 2 * B_SLOT_B)    // 106496
#define DYN_SMEM (META_B + TILE_M * C_LD * 4)  // 137216 (C tile epilogue > pipeline)

// Context split-T (fused softmax)
#define CSEG     32
#define CT       (T / CSEG)        // 64

// ---- scratch (no allocations allowed) ----
__device__ __half g_enc_h[(size_t)B * T * ENC];   // 128 MB
__device__ __half g_We_h[ENC * ATTN];
__device__ float  g_proj_dec[B * ATTN];
__device__ float  g_energy[B * T];
__device__ float  g_ctx_part[CSEG * B * ENC];     // 4 MB
__device__ int    g_mask_is_byte;

// ---------------------------------------------------------------------------
__device__ __forceinline__ uint32_t smem_u32(const void* p) {
    uint32_t a;
    asm("{ .reg .u64 t; cvta.to.shared.u64 t, %1; cvt.u32.u64 %0, t; }" : "=r"(a) : "l"(p));
    return a;
}
__device__ __forceinline__ float fast_tanh(float x) {
    float y; asm("tanh.approx.f32 %0, %1;" : "=f"(y) : "f"(x)); return y;
}
__device__ __forceinline__ void cp_async16(uint32_t s, const void* g) {
    asm volatile("cp.async.cg.shared.global [%0], [%1], 16;" :: "r"(s), "l"(g));
}
#define CP_COMMIT() asm volatile("cp.async.commit_group;" ::: "memory")
#define CP_WAIT(n)  asm volatile("cp.async.wait_group %0;" :: "n"(n) : "memory")

// ---------------------------------------------------------------------------
// Fused prologue: projdec (0-255), convert_we (256-287), mask detect (288).
// ---------------------------------------------------------------------------
__global__ void __launch_bounds__(256)
prep_kernel(const float* __restrict__ dec, const float* __restrict__ Wd,
            const float* __restrict__ We, const unsigned char* __restrict__ mask) {
    const int blk = blockIdx.x, tid = threadIdx.x;

    if (blk < 256) {
        __shared__ float sd[DEC];
        __shared__ float sp[256];
        const int b = blk >> 2, q = blk & 3;
        const int a = q * 64 + (tid & 63);
        const int kseg = tid >> 6;
        sd[tid]       = dec[b * DEC + tid];
        sd[tid + 256] = dec[b * DEC + tid + 256];
        __syncthreads();
        const float* wp = Wd + (size_t)(kseg * 128) * ATTN + a;
        const float* dp = sd + kseg * 128;
        float a0 = 0.f, a1 = 0.f, a2 = 0.f, a3 = 0.f;
        #pragma unroll 8
        for (int i = 0; i < 128; i += 4) {
            a0 = fmaf(dp[i + 0], wp[(size_t)(i + 0) * ATTN], a0);
            a1 = fmaf(dp[i + 1], wp[(size_t)(i + 1) * ATTN], a1);
            a2 = fmaf(dp[i + 2], wp[(size_t)(i + 2) * ATTN], a2);
            a3 = fmaf(dp[i + 3], wp[(size_t)(i + 3) * ATTN], a3);
        }
        sp[tid] = (a0 + a1) + (a2 + a3);
        __syncthreads();
        if (tid < 64)
            g_proj_dec[b * ATTN + q * 64 + tid] =
                sp[tid] + sp[tid + 64] + sp[tid + 128] + sp[tid + 192];
    } else if (blk < 288) {
        const int blk2 = blk - 256;
        const float4* in = (const float4*)We;
        uint2* out = (uint2*)g_We_h;
        #pragma unroll
        for (int j = 0; j < 4; j++) {
            int i = blk2 * 256 + tid + j * 8192;
            float4 x = in[i];
            union { uint2 u; __half2 h[2]; } cv;
            cv.h[0] = __floats2half2_rn(x.x, x.y);
            cv.h[1] = __floats2half2_rn(x.z, x.w);
            out[i] = cv.u;
        }
    } else {
        __shared__ int f;
        if (tid == 0) f = 0;
        __syncthreads();
        const uint4* m4 = (const uint4*)mask;
        uint32_t acc = 0;
        #pragma unroll 8
        for (int j = 0; j < 32; j++) {
            uint4 w = m4[tid + j * 256];
            acc |= (w.x | w.y | w.z | w.w) & 0xFFFFFF00u;
        }
        if (acc) atomicOr(&f, 1);
        __syncthreads();
        if (tid == 0) g_mask_is_byte = f;
    }
}

// ---------------------------------------------------------------------------
// Fused energy kernel: fp16 WMMA 128x256x512, f32 accum, warp tile 64x64.
// grid (T/128, B), block 256 (8 warps, 2Mx4N). 1 CTA/SM.
// A: reg double-buffer + in-register f32->half (also writes g_enc_h).
// B: 2-slot cp.async ring.
// ---------------------------------------------------------------------------
__device__ __forceinline__ void ldg_a(const float* __restrict__ enc_tile,
                                      int c, float4* r, int tid) {
    const float* p = enc_tile + c * KC;
    #pragma unroll
    for (int it = 0; it < 8; it++) {
        int idx = it * 256 + tid;                 // 2048 float4
        int row = idx >> 4, col4 = idx & 15;      // 128 rows x 16 float4
        r[it] = *(const float4*)(p + (size_t)row * ENC + col4 * 4);
    }
}

__device__ __forceinline__ void cvt_sts_a(const float4* r, int c, __half* aslot,
                                          __half* __restrict__ gdst_tile, int tid) {
    #pragma unroll
    for (int it = 0; it < 8; it++) {
        int idx = it * 256 + tid;
        int row = idx >> 4, col4 = idx & 15;
        union { uint2 u; __half2 h[2]; } cv;
        cv.h[0] = __floats2half2_rn(r[it].x, r[it].y);
        cv.h[1] = __floats2half2_rn(r[it].z, r[it].w);
        *(uint2*)(aslot + row * A_LD_H + col4 * 4) = cv.u;
        *(uint2*)(gdst_tile + (size_t)row * ENC + c * KC + col4 * 4) = cv.u;
    }
}

__device__ __forceinline__ void load_b(int c, uint32_t bslot_u, int tid) {
    const __half* bsrc = g_We_h + (size_t)c * KC * ATTN;
    #pragma unroll
    for (int it = 0; it < 8; it++) {
        int idx = it * 256 + tid;                 // 2048 x 16B
        int row = idx >> 5, seg = idx & 31;       // 64 rows x 32 segs
        cp_async16(bslot_u + (uint32_t)(row * B_LD_H + seg * 8) * 2,
                   bsrc + (size_t)row * ATTN + seg * 8);
    }
}

__global__ void __launch_bounds__(256, 1)
energy_wmma_kernel(const float* __restrict__ enc, const float* __restrict__ v) {
    extern __shared__ char dsm[];
    float* pd_s = (float*)dsm;
    float* v_s  = (float*)(dsm + ATTN * 4);
    float* c_s  = (float*)(dsm + META_B);

    const uint32_t sb = smem_u32(dsm);

    const int tid  = threadIdx.x;
    const int wid  = tid >> 5;
    const int wm   = wid & 1;          // 0..1 -> M offset wm*64
    const int wn   = wid >> 1;         // 0..3 -> N offset wn*64
    const int b    = blockIdx.y;
    const int t0   = blockIdx.x * TILE_M;
    const float* enc_tile = enc + ((size_t)b * T + t0) * ENC;
    __half* gdst_tile = g_enc_h + ((size_t)b * T + t0) * ENC;

    pd_s[tid] = g_proj_dec[b * ATTN + tid];
    v_s[tid]  = v[tid];

    // warp tile 64x64: 4 M-frags x 4 N-frags
    wmma::fragment<wmma::accumulator, 16, 16, 16, float> cf[4][4];
    #pragma unroll
    for (int i = 0; i < 4; i++)
        #pragma unroll
        for (int j = 0; j < 4; j++)
            wmma::fill_fragment(cf[i][j], 0.0f);

    float4 rnext[8];

    ldg_a(enc_tile, 0, rnext, tid);
    load_b(0, sb + B0_OFF, tid);  CP_COMMIT();
    cvt_sts_a(rnext, 0, (__half*)(dsm + A0_OFF), gdst_tile, tid);
    ldg_a(enc_tile, 1, rnext, tid);
    load_b(1, sb + B0_OFF + B_SLOT_B, tid);  CP_COMMIT();
    CP_WAIT(1);
    __syncthreads();

    #pragma unroll 1
    for (int c = 0; c < NCHUNK; c++) {
        if (c + 1 < NCHUNK)
            cvt_sts_a(rnext, c + 1,
                      (__half*)(dsm + A0_OFF + ((c + 1) & 1) * A_SLOT_B),
                      gdst_tile, tid);
        if (c + 2 < NCHUNK)
            ldg_a(enc_tile, c + 2, rnext, tid);

        const __half* a_s = (const __half*)(dsm + A0_OFF + (c & 1) * A_SLOT_B);
        const __half* b_s = (const __half*)(dsm + B0_OFF + (c & 1) * B_SLOT_B);
        #pragma unroll
        for (int ks = 0; ks < KC / 16; ks++) {
            wmma::fragment<wmma::matrix_a, 16, 16, 16, __half, wmma::row_major> af[4];
            #pragma unroll
            for (int i = 0; i < 4; i++)
                wmma::load_matrix_sync(af[i],
                    a_s + (size_t)(wm * 64 + i * 16) * A_LD_H + ks * 16, A_LD_H);
            #pragma unroll
            for (int j = 0; j < 4; j++) {
                wmma::fragment<wmma::matrix_b, 16, 16, 16, __half, wmma::row_major> bfrag;
                wmma::load_matrix_sync(bfrag,
                    b_s + (size_t)(ks * 16) * B_LD_H + wn * 64 + j * 16, B_LD_H);
                #pragma unroll
                for (int i = 0; i < 4; i++)
                    wmma::mma_sync(cf[i][j], af[i], bfrag, cf[i][j]);
            }
        }

        if (c + 1 < NCHUNK) CP_WAIT(0);
        __syncthreads();
        if (c + 2 < NCHUNK) {
            load_b(c + 2, sb + B0_OFF + (c & 1) * B_SLOT_B, tid);
            CP_COMMIT();
        }
    }

    // store C tile (128 x 256, ld 264) and reduce
    #pragma unroll
    for (int i = 0; i < 4; i++)
        #pragma unroll
        for (int j = 0; j < 4; j++)
            wmma::store_matrix_sync(
                c_s + (size_t)(wm * 64 + i * 16) * C_LD + wn * 64 + j * 16,
                cf[i][j], C_LD, wmma::mem_row_major);
    __syncthreads();

    // 256 threads: row = tid>>1 (128 rows), half-row of 128 cols each
    const int row = tid >> 1, h = tid & 1;
    const float* crow = c_s + (size_t)row * C_LD + h * 128;
    const float* pdq  = pd_s + h * 128;
    const float* vq   = v_s + h * 128;
    float e = 0.f;
    #pragma unroll 8
    for (int j = 0; j < 128; j++)
        e = fmaf(fast_tanh(crow[j] + pdq[j]), vq[j], e);
    e += __shfl_xor_sync(0xffffffffu, e, 1);
    if (h == 0)
        g_energy[b * T + t0 + row] = e;
}

// ---------------------------------------------------------------------------
// Fused softmax + context partials: grid (B, CSEG), block 128.  (R10 exact)
// ---------------------------------------------------------------------------
__global__ void __launch_bounds__(128)
ctx_softmax_kernel(const void* __restrict__ mask,
                   float* __restrict__ attn_out) {
    __shared__ float sred[8];
    __shared__ float sw[CT];

    const int b   = blockIdx.x;
    const int seg = blockIdx.y;
    const int tb  = seg * CT;
    const int tid = threadIdx.x;

    const bool isbyte = (g_mask_is_byte != 0);
    const unsigned char* mb = (const unsigned char*)mask;
    const int*           mi = (const int*)mask;

    float e[16];
    #pragma unroll
    for (int j = 0; j < 16; j++) {
        const int i = b * T + tid + j * 128;
        const bool m = isbyte ? (mb[i] != 0) : (mi[i] != 0);
        e[j] = m ? -INFINITY : g_energy[i];
    }
    float mx = e[0];
    #pragma unroll
    for (int j = 1; j < 16; j++) mx = fmaxf(mx, e[j]);
    #pragma unroll
    for (int o = 16; o > 0; o >>= 1)
        mx = fmaxf(mx, __shfl_xor_sync(0xffffffffu, mx, o));
    if ((tid & 31) == 0) sred[tid >> 5] = mx;
    __syncthreads();
    if (tid < 32) {
        float t = (tid < 4) ? sred[tid] : -INFINITY;
        #pragma unroll
        for (int o = 2; o > 0; o >>= 1)
            t = fmaxf(t, __shfl_xor_sync(0xffffffffu, t, o));
        if (tid == 0) sred[4] = t;
    }
    __syncthreads();
    mx = sred[4];

    const bool allmasked = !(mx > -INFINITY);

    float s = 0.f;
    #pragma unroll
    for (int j = 0; j < 16; j++)
        s += (allmasked || e[j] == -INFINITY) ? 0.f : expf(e[j] - mx);
    #pragma unroll
    for (int o = 16; o > 0; o >>= 1)
        s += __shfl_xor_sync(0xffffffffu, s, o);
    __syncthreads();
    if ((tid & 31) == 0) sred[tid >> 5] = s;
    __syncthreads();
    if (tid < 32) {
        float t = (tid < 4) ? sred[tid] : 0.f;
        #pragma unroll
        for (int o = 2; o > 0; o >>= 1)
            t += __shfl_xor_sync(0xffffffffu, t, o);
        if (tid == 0) sred[5] = t;
    }
    __syncthreads();
    s = sred[5];
    const float inv = (s > 0.f) ? (1.f / s) : 0.f;

    if (tid < CT) {
        const int i = b * T + tb + tid;
        const bool m = isbyte ? (mb[i] != 0) : (mi[i] != 0);
        const float ev = (allmasked || m) ? -INFINITY : g_energy[i];
        const float w = (ev == -INFINITY) ? 0.f : expf(ev - mx) * inv;
        sw[tid] = w;
        attn_out[i] = w;
    }
    __syncthreads();

    const uint2* ep = (const uint2*)(g_enc_h + ((size_t)b * T + tb) * ENC) + tid;
    float4 acc = {0.f, 0.f, 0.f, 0.f};
    #pragma unroll 8
    for (int t = 0; t < CT; t++) {
        union { uint2 u; __half2 h[2]; } w;
        w.u = ep[(size_t)t * (ENC / 4)];
        const float sc = sw[t];
        float2 f0 = __half22float2(w.h[0]);
        float2 f1 = __half22float2(w.h[1]);
        acc.x = fmaf(sc, f0.x, acc.x);
        acc.y = fmaf(sc, f0.y, acc.y);
        acc.z = fmaf(sc, f1.x, acc.z);
        acc.w = fmaf(sc, f1.y, acc.w);
    }
    *(float4*)(g_ctx_part + ((size_t)seg * B + b) * ENC + tid * 4) = acc;
}

// ---------------------------------------------------------------------------
// context reduce over CSEG partials: grid B, block 512  (R10 exact)
// ---------------------------------------------------------------------------
__global__ void __launch_bounds__(512)
context_reduce_kernel(float* __restrict__ ctx) {
    const int b = blockIdx.x, e = threadIdx.x;
    float s = 0.f;
    #pragma unroll
    for (int seg = 0; seg < CSEG; seg++)
        s += g_ctx_part[((size_t)seg * B + b) * ENC + e];
    ctx[b * ENC + e] = s;
}

// ---------------------------------------------------------------------------
extern "C" void kernel_launch(void* const* d_in, const int* in_sizes, int n_in,
                              void* d_out, int out_size) {
    const float* enc  = (const float*)d_in[0];
    const float* dec  = (const float*)d_in[1];
    const void*  mask = d_in[2];
    const float* We   = (const float*)d_in[3];
    const float* Wd   = (const float*)d_in[4];
    const float* v    = (const float*)d_in[5];

    float* out_ctx  = (float*)d_out;
    float* out_attn = out_ctx + B * ENC;

    cudaFuncSetAttribute(energy_wmma_kernel,
                         cudaFuncAttributeMaxDynamicSharedMemorySize, DYN_SMEM);

    prep_kernel<<<289, 256>>>(dec, Wd, We, (const unsigned char*)mask);
    energy_wmma_kernel<<<dim3(T / TILE_M, B), 256, DYN_SMEM>>>(enc, v);
    ctx_softmax_kernel<<<dim3(B, CSEG), 128>>>(mask, out_attn);
    context_reduce_kernel<<<B, 512>>>(out_ctx);
}

// round 13
// speedup vs baseline: 1.5455x; 1.0289x over previous
#include <cuda_runtime.h>
#include <cuda_fp16.h>
#include <math.h>
#include <stdint.h>
#include <mma.h>

using namespace nvcuda;

// Problem constants
#define B    64
#define T    2048
#define ENC  512
#define DEC  512
#define ATTN 256

// Energy GEMM tiling: 128x256 CTA tile, 8 warps, warp tile 64x64, persistent
#define TILE_M  128
#define KC      64
#define CPT     8                   // chunks per tile (ENC/KC)
#define NTILES  1024                // (T/TILE_M) * B = 16 * 64
#define TPB     16                  // tiles per batch row (T/TILE_M)
#define EGRID   148                 // persistent grid

#define A_LD_H  72
#define B_LD_H  264
#define C_LD2   136                 // two-pass epilogue C ld (floats)

#define A_SLOT_B (TILE_M * A_LD_H * 2)      // 18432, 2 slots
#define B_SLOT_B (KC * B_LD_H * 2)          // 33792, 2 slots
#define META_B   2048
#define A0_OFF   META_B
#define B0_OFF   (META_B + 2 * A_SLOT_B)    // 38912
#define C_OFF    (B0_OFF + 2 * B_SLOT_B)    // 106496
#define C_BYTES  (TILE_M * C_LD2 * 4)       // 69632
#define DYN_SMEM (C_OFF + C_BYTES)          // 176128

// Context split-T (fused softmax)
#define CSEG     32
#define CT       (T / CSEG)        // 64

// ---- scratch (no allocations allowed) ----
__device__ __half g_enc_h[(size_t)B * T * ENC];   // 128 MB
__device__ __half g_We_h[ENC * ATTN];
__device__ float  g_proj_dec[B * ATTN];
__device__ float  g_energy[B * T];
__device__ float  g_ctx_part[CSEG * B * ENC];     // 4 MB
__device__ int    g_mask_is_byte;

// ---------------------------------------------------------------------------
__device__ __forceinline__ uint32_t smem_u32(const void* p) {
    uint32_t a;
    asm("{ .reg .u64 t; cvta.to.shared.u64 t, %1; cvt.u32.u64 %0, t; }" : "=r"(a) : "l"(p));
    return a;
}
__device__ __forceinline__ float fast_tanh(float x) {
    float y; asm("tanh.approx.f32 %0, %1;" : "=f"(y) : "f"(x)); return y;
}
__device__ __forceinline__ void cp_async16(uint32_t s, const void* g) {
    asm volatile("cp.async.cg.shared.global [%0], [%1], 16;" :: "r"(s), "l"(g));
}
#define CP_COMMIT() asm volatile("cp.async.commit_group;" ::: "memory")
#define CP_WAIT(n)  asm volatile("cp.async.wait_group %0;" :: "n"(n) : "memory")

// ---------------------------------------------------------------------------
// Fused prologue: projdec (0-255), convert_we (256-287), mask detect (288).
// ---------------------------------------------------------------------------
__global__ void __launch_bounds__(256)
prep_kernel(const float* __restrict__ dec, const float* __restrict__ Wd,
            const float* __restrict__ We, const unsigned char* __restrict__ mask) {
    const int blk = blockIdx.x, tid = threadIdx.x;

    if (blk < 256) {
        __shared__ float sd[DEC];
        __shared__ float sp[256];
        const int b = blk >> 2, q = blk & 3;
        const int a = q * 64 + (tid & 63);
        const int kseg = tid >> 6;
        sd[tid]       = dec[b * DEC + tid];
        sd[tid + 256] = dec[b * DEC + tid + 256];
        __syncthreads();
        const float* wp = Wd + (size_t)(kseg * 128) * ATTN + a;
        const float* dp = sd + kseg * 128;
        float a0 = 0.f, a1 = 0.f, a2 = 0.f, a3 = 0.f;
        #pragma unroll 8
        for (int i = 0; i < 128; i += 4) {
            a0 = fmaf(dp[i + 0], wp[(size_t)(i + 0) * ATTN], a0);
            a1 = fmaf(dp[i + 1], wp[(size_t)(i + 1) * ATTN], a1);
            a2 = fmaf(dp[i + 2], wp[(size_t)(i + 2) * ATTN], a2);
            a3 = fmaf(dp[i + 3], wp[(size_t)(i + 3) * ATTN], a3);
        }
        sp[tid] = (a0 + a1) + (a2 + a3);
        __syncthreads();
        if (tid < 64)
            g_proj_dec[b * ATTN + q * 64 + tid] =
                sp[tid] + sp[tid + 64] + sp[tid + 128] + sp[tid + 192];
    } else if (blk < 288) {
        const int blk2 = blk - 256;
        const float4* in = (const float4*)We;
        uint2* out = (uint2*)g_We_h;
        #pragma unroll
        for (int j = 0; j < 4; j++) {
            int i = blk2 * 256 + tid + j * 8192;
            float4 x = in[i];
            union { uint2 u; __half2 h[2]; } cv;
            cv.h[0] = __floats2half2_rn(x.x, x.y);
            cv.h[1] = __floats2half2_rn(x.z, x.w);
            out[i] = cv.u;
        }
    } else {
        __shared__ int f;
        if (tid == 0) f = 0;
        __syncthreads();
        const uint4* m4 = (const uint4*)mask;
        uint32_t acc = 0;
        #pragma unroll 8
        for (int j = 0; j < 32; j++) {
            uint4 w = m4[tid + j * 256];
            acc |= (w.x | w.y | w.z | w.w) & 0xFFFFFF00u;
        }
        if (acc) atomicOr(&f, 1);
        __syncthreads();
        if (tid == 0) g_mask_is_byte = f;
    }
}

// ---------------------------------------------------------------------------
// Persistent energy kernel: fp16 WMMA 128x256x512, f32 accum, 64x64 warp
// tiles. grid 148, each CTA grid-strides over tiles; pipeline stays warm
// across tile boundaries (single fill per CTA). Two-pass f32 epilogue.
// ---------------------------------------------------------------------------
__device__ __forceinline__ void tile_of(int gc, int bx, int& bb, int& tx) {
    const int tile_id = bx + (gc >> 3) * EGRID;
    tx = tile_id & (TPB - 1);
    bb = tile_id >> 4;
}

__device__ __forceinline__ void ldg_a(const float* __restrict__ enc, int gc,
                                      int bx, float4* r, int tid) {
    int bb, tx; tile_of(gc, bx, bb, tx);
    const float* p = enc + ((size_t)bb * T + tx * TILE_M) * ENC + (gc & 7) * KC;
    #pragma unroll
    for (int it = 0; it < 8; it++) {
        int idx = it * 256 + tid;
        int row = idx >> 4, col4 = idx & 15;
        r[it] = *(const float4*)(p + (size_t)row * ENC + col4 * 4);
    }
}

__device__ __forceinline__ void cvt_sts_a(const float4* r, int gc, int bx,
                                          __half* aslot, int tid) {
    int bb, tx; tile_of(gc, bx, bb, tx);
    __half* gdst = g_enc_h + ((size_t)bb * T + tx * TILE_M) * ENC + (gc & 7) * KC;
    #pragma unroll
    for (int it = 0; it < 8; it++) {
        int idx = it * 256 + tid;
        int row = idx >> 4, col4 = idx & 15;
        union { uint2 u; __half2 h[2]; } cv;
        cv.h[0] = __floats2half2_rn(r[it].x, r[it].y);
        cv.h[1] = __floats2half2_rn(r[it].z, r[it].w);
        *(uint2*)(aslot + row * A_LD_H + col4 * 4) = cv.u;
        *(uint2*)(gdst + (size_t)row * ENC + col4 * 4) = cv.u;
    }
}

__device__ __forceinline__ void load_b(int gc, uint32_t bslot_u, int tid) {
    const __half* bsrc = g_We_h + (size_t)(gc & 7) * KC * ATTN;
    #pragma unroll
    for (int it = 0; it < 8; it++) {
        int idx = it * 256 + tid;
        int row = idx >> 5, seg = idx & 31;
        cp_async16(bslot_u + (uint32_t)(row * B_LD_H + seg * 8) * 2,
                   bsrc + (size_t)row * ATTN + seg * 8);
    }
}

__global__ void __launch_bounds__(256, 1)
energy_wmma_kernel(const float* __restrict__ enc, const float* __restrict__ v) {
    extern __shared__ char dsm[];
    float* pd_s = (float*)dsm;
    float* v_s  = (float*)(dsm + ATTN * 4);
    float* c2_s = (float*)(dsm + C_OFF);

    const uint32_t sb = smem_u32(dsm);
    const int tid = threadIdx.x;
    const int wid = tid >> 5;
    const int wm  = wid & 1;           // M offset wm*64
    const int wn  = wid >> 1;          // N offset wn*64
    const int bx  = blockIdx.x;

    const int NT   = (NTILES - 1 - bx) / EGRID + 1;   // tiles for this CTA
    const int GTOT = NT * CPT;

    v_s[tid] = v[tid];

    wmma::fragment<wmma::accumulator, 16, 16, 16, float> cf[4][4];
    #pragma unroll
    for (int i = 0; i < 4; i++)
        #pragma unroll
        for (int j = 0; j < 4; j++)
            wmma::fill_fragment(cf[i][j], 0.0f);

    float4 rnext[8];

    // single pipeline fill
    ldg_a(enc, 0, bx, rnext, tid);
    load_b(0, sb + B0_OFF, tid);  CP_COMMIT();
    cvt_sts_a(rnext, 0, bx, (__half*)(dsm + A0_OFF), tid);
    ldg_a(enc, 1, bx, rnext, tid);
    load_b(1, sb + B0_OFF + B_SLOT_B, tid);  CP_COMMIT();
    CP_WAIT(1);
    __syncthreads();

    #pragma unroll 1
    for (int gc = 0; gc < GTOT; gc++) {
        if (gc + 1 < GTOT)
            cvt_sts_a(rnext, gc + 1, bx,
                      (__half*)(dsm + A0_OFF + ((gc + 1) & 1) * A_SLOT_B), tid);
        if (gc + 2 < GTOT)
            ldg_a(enc, gc + 2, bx, rnext, tid);

        const __half* a_s = (const __half*)(dsm + A0_OFF + (gc & 1) * A_SLOT_B);
        const __half* b_s = (const __half*)(dsm + B0_OFF + (gc & 1) * B_SLOT_B);
        #pragma unroll
        for (int ks = 0; ks < KC / 16; ks++) {
            wmma::fragment<wmma::matrix_a, 16, 16, 16, __half, wmma::row_major> af[4];
            #pragma unroll
            for (int i = 0; i < 4; i++)
                wmma::load_matrix_sync(af[i],
                    a_s + (size_t)(wm * 64 + i * 16) * A_LD_H + ks * 16, A_LD_H);
            #pragma unroll
            for (int j = 0; j < 4; j++) {
                wmma::fragment<wmma::matrix_b, 16, 16, 16, __half, wmma::row_major> bfrag;
                wmma::load_matrix_sync(bfrag,
                    b_s + (size_t)(ks * 16) * B_LD_H + wn * 64 + j * 16, B_LD_H);
                #pragma unroll
                for (int i = 0; i < 4; i++)
                    wmma::mma_sync(cf[i][j], af[i], bfrag, cf[i][j]);
            }
        }

        if (gc + 1 < GTOT) CP_WAIT(0);
        __syncthreads();
        if (gc + 2 < GTOT) {
            load_b(gc + 2, sb + B0_OFF + (gc & 1) * B_SLOT_B, tid);
            CP_COMMIT();
        }

        // ---- epilogue every 8 chunks (tile finished) ----
        if ((gc & 7) == 7) {
            int bb, tx; tile_of(gc, bx, bb, tx);
            pd_s[tid] = g_proj_dec[bb * ATTN + tid];

            const int row = tid >> 1, h = tid & 1;
            float e = 0.f;
            #pragma unroll
            for (int p = 0; p < 2; p++) {
                __syncthreads();                       // pd ready / C reusable
                if ((wn >> 1) == p) {
                    #pragma unroll
                    for (int i = 0; i < 4; i++)
                        #pragma unroll
                        for (int j = 0; j < 4; j++)
                            wmma::store_matrix_sync(
                                c2_s + (size_t)(wm * 64 + i * 16) * C_LD2
                                     + (wn & 1) * 64 + j * 16,
                                cf[i][j], C_LD2, wmma::mem_row_major);
                }
                __syncthreads();
                const float* crow = c2_s + (size_t)row * C_LD2 + h * 64;
                const float* pdq  = pd_s + p * 128 + h * 64;
                const float* vq   = v_s + p * 128 + h * 64;
                #pragma unroll 8
                for (int j = 0; j < 64; j++)
                    e = fmaf(fast_tanh(crow[j] + pdq[j]), vq[j], e);
            }
            e += __shfl_xor_sync(0xffffffffu, e, 1);
            if (h == 0)
                g_energy[bb * T + tx * TILE_M + row] = e;

            #pragma unroll
            for (int i = 0; i < 4; i++)
                #pragma unroll
                for (int j = 0; j < 4; j++)
                    wmma::fill_fragment(cf[i][j], 0.0f);
            __syncthreads();                           // C region done
        }
    }
}

// ---------------------------------------------------------------------------
// Fused softmax + context partials: grid (B, CSEG), block 128.
// ---------------------------------------------------------------------------
__global__ void __launch_bounds__(128)
ctx_softmax_kernel(const void* __restrict__ mask,
                   float* __restrict__ attn_out) {
    __shared__ float sred[8];
    __shared__ float sw[CT];

    const int b   = blockIdx.x;
    const int seg = blockIdx.y;
    const int tb  = seg * CT;
    const int tid = threadIdx.x;

    const bool isbyte = (g_mask_is_byte != 0);
    const unsigned char* mb = (const unsigned char*)mask;
    const int*           mi = (const int*)mask;

    float e[16];
    #pragma unroll
    for (int j = 0; j < 16; j++) {
        const int i = b * T + tid + j * 128;
        const bool m = isbyte ? (mb[i] != 0) : (mi[i] != 0);
        e[j] = m ? -INFINITY : g_energy[i];
    }
    float mx = e[0];
    #pragma unroll
    for (int j = 1; j < 16; j++) mx = fmaxf(mx, e[j]);
    #pragma unroll
    for (int o = 16; o > 0; o >>= 1)
        mx = fmaxf(mx, __shfl_xor_sync(0xffffffffu, mx, o));
    if ((tid & 31) == 0) sred[tid >> 5] = mx;
    __syncthreads();
    if (tid < 32) {
        float t = (tid < 4) ? sred[tid] : -INFINITY;
        #pragma unroll
        for (int o = 2; o > 0; o >>= 1)
            t = fmaxf(t, __shfl_xor_sync(0xffffffffu, t, o));
        if (tid == 0) sred[4] = t;
    }
    __syncthreads();
    mx = sred[4];

    const bool allmasked = !(mx > -INFINITY);

    float s = 0.f;
    #pragma unroll
    for (int j = 0; j < 16; j++)
        s += (allmasked || e[j] == -INFINITY) ? 0.f : expf(e[j] - mx);
    #pragma unroll
    for (int o = 16; o > 0; o >>= 1)
        s += __shfl_xor_sync(0xffffffffu, s, o);
    __syncthreads();
    if ((tid & 31) == 0) sred[tid >> 5] = s;
    __syncthreads();
    if (tid < 32) {
        float t = (tid < 4) ? sred[tid] : 0.f;
        #pragma unroll
        for (int o = 2; o > 0; o >>= 1)
            t += __shfl_xor_sync(0xffffffffu, t, o);
        if (tid == 0) sred[5] = t;
    }
    __syncthreads();
    s = sred[5];
    const float inv = (s > 0.f) ? (1.f / s) : 0.f;

    if (tid < CT) {
        const int i = b * T + tb + tid;
        const bool m = isbyte ? (mb[i] != 0) : (mi[i] != 0);
        const float ev = (allmasked || m) ? -INFINITY : g_energy[i];
        const float w = (ev == -INFINITY) ? 0.f : expf(ev - mx) * inv;
        sw[tid] = w;
        attn_out[i] = w;
    }
    __syncthreads();

    const uint2* ep = (const uint2*)(g_enc_h + ((size_t)b * T + tb) * ENC) + tid;
    float4 acc = {0.f, 0.f, 0.f, 0.f};
    #pragma unroll 8
    for (int t = 0; t < CT; t++) {
        union { uint2 u; __half2 h[2]; } w;
        w.u = ep[(size_t)t * (ENC / 4)];
        const float sc = sw[t];
        float2 f0 = __half22float2(w.h[0]);
        float2 f1 = __half22float2(w.h[1]);
        acc.x = fmaf(sc, f0.x, acc.x);
        acc.y = fmaf(sc, f0.y, acc.y);
        acc.z = fmaf(sc, f1.x, acc.z);
        acc.w = fmaf(sc, f1.y, acc.w);
    }
    *(float4*)(g_ctx_part + ((size_t)seg * B + b) * ENC + tid * 4) = acc;
}

// ---------------------------------------------------------------------------
// context reduce over CSEG partials: grid B, block 512
// ---------------------------------------------------------------------------
__global__ void __launch_bounds__(512)
context_reduce_kernel(float* __restrict__ ctx) {
    const int b = blockIdx.x, e = threadIdx.x;
    float s = 0.f;
    #pragma unroll
    for (int seg = 0; seg < CSEG; seg++)
        s += g_ctx_part[((size_t)seg * B + b) * ENC + e];
    ctx[b * ENC + e] = s;
}

// ---------------------------------------------------------------------------
extern "C" void kernel_launch(void* const* d_in, const int* in_sizes, int n_in,
                              void* d_out, int out_size) {
    const float* enc  = (const float*)d_in[0];
    const float* dec  = (const float*)d_in[1];
    const void*  mask = d_in[2];
    const float* We   = (const float*)d_in[3];
    const float* Wd   = (const float*)d_in[4];
    const float* v    = (const float*)d_in[5];

    float* out_ctx  = (float*)d_out;
    float* out_attn = out_ctx + B * ENC;

    cudaFuncSetAttribute(energy_wmma_kernel,
                         cudaFuncAttributeMaxDynamicSharedMemorySize, DYN_SMEM);

    prep_kernel<<<289, 256>>>(dec, Wd, We, (const unsigned char*)mask);
    energy_wmma_kernel<<<EGRID, 256, DYN_SMEM>>>(enc, v);
    ctx_softmax_kernel<<<dim3(B, CSEG), 128>>>(mask, out_attn);
    context_reduce_kernel<<<B, 512>>>(out_ctx);
}

// round 14
// speedup vs baseline: 1.5546x; 1.0059x over previous
#include <cuda_runtime.h>
#include <cuda_fp16.h>
#include <math.h>
#include <stdint.h>
#include <mma.h>

using namespace nvcuda;

// Problem constants
#define B    64
#define T    2048
#define ENC  512
#define DEC  512
#define ATTN 256

// Energy GEMM tiling: 128x256 CTA tile, 8 warps, warp tile 64x64, persistent
#define TILE_M  128
#define KC      64
#define CPT     8                   // chunks per tile (ENC/KC)
#define NTILES  1024                // (T/TILE_M) * B = 16 * 64
#define TPB     16                  // tiles per batch row (T/TILE_M)
#define EGRID   148                 // persistent grid

#define A_LD_H  72
#define B_LD_H  264
#define C_LD2   136                 // two-pass epilogue C ld (floats)

#define A_SLOT_B (TILE_M * A_LD_H * 2)      // 18432, 2 slots
#define B_SLOT_B (KC * B_LD_H * 2)          // 33792, 2 slots
#define META_B   2048
#define A0_OFF   META_B
#define B0_OFF   (META_B + 2 * A_SLOT_B)    // 38912
#define C_OFF    (B0_OFF + 2 * B_SLOT_B)    // 106496
#define C_BYTES  (TILE_M * C_LD2 * 4)       // 69632
#define DYN_SMEM (C_OFF + C_BYTES)          // 176128

// Context split-T (fused softmax)
#define CSEG     32
#define CT       (T / CSEG)        // 64

// ---- scratch (no allocations allowed) ----
__device__ __half g_enc_h[(size_t)B * T * ENC];   // 128 MB
__device__ __half g_We_h[ENC * ATTN];
__device__ float  g_proj_dec[B * ATTN];
__device__ float  g_energy[B * T];
__device__ int    g_mask_is_byte;

// ---------------------------------------------------------------------------
__device__ __forceinline__ uint32_t smem_u32(const void* p) {
    uint32_t a;
    asm("{ .reg .u64 t; cvta.to.shared.u64 t, %1; cvt.u32.u64 %0, t; }" : "=r"(a) : "l"(p));
    return a;
}
__device__ __forceinline__ float fast_tanh(float x) {
    float y; asm("tanh.approx.f32 %0, %1;" : "=f"(y) : "f"(x)); return y;
}
__device__ __forceinline__ void cp_async16(uint32_t s, const void* g) {
    asm volatile("cp.async.cg.shared.global [%0], [%1], 16;" :: "r"(s), "l"(g));
}
#define CP_COMMIT() asm volatile("cp.async.commit_group;" ::: "memory")
#define CP_WAIT(n)  asm volatile("cp.async.wait_group %0;" :: "n"(n) : "memory")

// ---------------------------------------------------------------------------
// Fused prologue: projdec (0-255), convert_we (256-287), mask detect (288),
// zero out_ctx (289 — required every launch: context accumulates via atomics).
// ---------------------------------------------------------------------------
__global__ void __launch_bounds__(256)
prep_kernel(const float* __restrict__ dec, const float* __restrict__ Wd,
            const float* __restrict__ We, const unsigned char* __restrict__ mask,
            float* __restrict__ out_ctx) {
    const int blk = blockIdx.x, tid = threadIdx.x;

    if (blk < 256) {
        __shared__ float sd[DEC];
        __shared__ float sp[256];
        const int b = blk >> 2, q = blk & 3;
        const int a = q * 64 + (tid & 63);
        const int kseg = tid >> 6;
        sd[tid]       = dec[b * DEC + tid];
        sd[tid + 256] = dec[b * DEC + tid + 256];
        __syncthreads();
        const float* wp = Wd + (size_t)(kseg * 128) * ATTN + a;
        const float* dp = sd + kseg * 128;
        float a0 = 0.f, a1 = 0.f, a2 = 0.f, a3 = 0.f;
        #pragma unroll 8
        for (int i = 0; i < 128; i += 4) {
            a0 = fmaf(dp[i + 0], wp[(size_t)(i + 0) * ATTN], a0);
            a1 = fmaf(dp[i + 1], wp[(size_t)(i + 1) * ATTN], a1);
            a2 = fmaf(dp[i + 2], wp[(size_t)(i + 2) * ATTN], a2);
            a3 = fmaf(dp[i + 3], wp[(size_t)(i + 3) * ATTN], a3);
        }
        sp[tid] = (a0 + a1) + (a2 + a3);
        __syncthreads();
        if (tid < 64)
            g_proj_dec[b * ATTN + q * 64 + tid] =
                sp[tid] + sp[tid + 64] + sp[tid + 128] + sp[tid + 192];
    } else if (blk < 288) {
        const int blk2 = blk - 256;
        const float4* in = (const float4*)We;
        uint2* out = (uint2*)g_We_h;
        #pragma unroll
        for (int j = 0; j < 4; j++) {
            int i = blk2 * 256 + tid + j * 8192;
            float4 x = in[i];
            union { uint2 u; __half2 h[2]; } cv;
            cv.h[0] = __floats2half2_rn(x.x, x.y);
            cv.h[1] = __floats2half2_rn(x.z, x.w);
            out[i] = cv.u;
        }
    } else if (blk == 288) {
        __shared__ int f;
        if (tid == 0) f = 0;
        __syncthreads();
        const uint4* m4 = (const uint4*)mask;
        uint32_t acc = 0;
        #pragma unroll 8
        for (int j = 0; j < 32; j++) {
            uint4 w = m4[tid + j * 256];
            acc |= (w.x | w.y | w.z | w.w) & 0xFFFFFF00u;
        }
        if (acc) atomicOr(&f, 1);
        __syncthreads();
        if (tid == 0) g_mask_is_byte = f;
    } else {
        // zero out_ctx: B*ENC = 32768 floats = 8192 float4
        float4 z = {0.f, 0.f, 0.f, 0.f};
        float4* o4 = (float4*)out_ctx;
        #pragma unroll
        for (int j = 0; j < 32; j++)
            o4[tid + j * 256] = z;
    }
}

// ---------------------------------------------------------------------------
// Persistent energy kernel (R13 exact): fp16 WMMA 128x256x512, f32 accum,
// 64x64 warp tiles, warm pipeline across tiles, two-pass f32 epilogue.
// ---------------------------------------------------------------------------
__device__ __forceinline__ void tile_of(int gc, int bx, int& bb, int& tx) {
    const int tile_id = bx + (gc >> 3) * EGRID;
    tx = tile_id & (TPB - 1);
    bb = tile_id >> 4;
}

__device__ __forceinline__ void ldg_a(const float* __restrict__ enc, int gc,
                                      int bx, float4* r, int tid) {
    int bb, tx; tile_of(gc, bx, bb, tx);
    const float* p = enc + ((size_t)bb * T + tx * TILE_M) * ENC + (gc & 7) * KC;
    #pragma unroll
    for (int it = 0; it < 8; it++) {
        int idx = it * 256 + tid;
        int row = idx >> 4, col4 = idx & 15;
        r[it] = *(const float4*)(p + (size_t)row * ENC + col4 * 4);
    }
}

__device__ __forceinline__ void cvt_sts_a(const float4* r, int gc, int bx,
                                          __half* aslot, int tid) {
    int bb, tx; tile_of(gc, bx, bb, tx);
    __half* gdst = g_enc_h + ((size_t)bb * T + tx * TILE_M) * ENC + (gc & 7) * KC;
    #pragma unroll
    for (int it = 0; it < 8; it++) {
        int idx = it * 256 + tid;
        int row = idx >> 4, col4 = idx & 15;
        union { uint2 u; __half2 h[2]; } cv;
        cv.h[0] = __floats2half2_rn(r[it].x, r[it].y);
        cv.h[1] = __floats2half2_rn(r[it].z, r[it].w);
        *(uint2*)(aslot + row * A_LD_H + col4 * 4) = cv.u;
        *(uint2*)(gdst + (size_t)row * ENC + col4 * 4) = cv.u;
    }
}

__device__ __forceinline__ void load_b(int gc, uint32_t bslot_u, int tid) {
    const __half* bsrc = g_We_h + (size_t)(gc & 7) * KC * ATTN;
    #pragma unroll
    for (int it = 0; it < 8; it++) {
        int idx = it * 256 + tid;
        int row = idx >> 5, seg = idx & 31;
        cp_async16(bslot_u + (uint32_t)(row * B_LD_H + seg * 8) * 2,
                   bsrc + (size_t)row * ATTN + seg * 8);
    }
}

__global__ void __launch_bounds__(256, 1)
energy_wmma_kernel(const float* __restrict__ enc, const float* __restrict__ v) {
    extern __shared__ char dsm[];
    float* pd_s = (float*)dsm;
    float* v_s  = (float*)(dsm + ATTN * 4);
    float* c2_s = (float*)(dsm + C_OFF);

    const uint32_t sb = smem_u32(dsm);
    const int tid = threadIdx.x;
    const int wid = tid >> 5;
    const int wm  = wid & 1;
    const int wn  = wid >> 1;
    const int bx  = blockIdx.x;

    const int NT   = (NTILES - 1 - bx) / EGRID + 1;
    const int GTOT = NT * CPT;

    v_s[tid] = v[tid];

    wmma::fragment<wmma::accumulator, 16, 16, 16, float> cf[4][4];
    #pragma unroll
    for (int i = 0; i < 4; i++)
        #pragma unroll
        for (int j = 0; j < 4; j++)
            wmma::fill_fragment(cf[i][j], 0.0f);

    float4 rnext[8];

    ldg_a(enc, 0, bx, rnext, tid);
    load_b(0, sb + B0_OFF, tid);  CP_COMMIT();
    cvt_sts_a(rnext, 0, bx, (__half*)(dsm + A0_OFF), tid);
    ldg_a(enc, 1, bx, rnext, tid);
    load_b(1, sb + B0_OFF + B_SLOT_B, tid);  CP_COMMIT();
    CP_WAIT(1);
    __syncthreads();

    #pragma unroll 1
    for (int gc = 0; gc < GTOT; gc++) {
        if (gc + 1 < GTOT)
            cvt_sts_a(rnext, gc + 1, bx,
                      (__half*)(dsm + A0_OFF + ((gc + 1) & 1) * A_SLOT_B), tid);
        if (gc + 2 < GTOT)
            ldg_a(enc, gc + 2, bx, rnext, tid);

        const __half* a_s = (const __half*)(dsm + A0_OFF + (gc & 1) * A_SLOT_B);
        const __half* b_s = (const __half*)(dsm + B0_OFF + (gc & 1) * B_SLOT_B);
        #pragma unroll
        for (int ks = 0; ks < KC / 16; ks++) {
            wmma::fragment<wmma::matrix_a, 16, 16, 16, __half, wmma::row_major> af[4];
            #pragma unroll
            for (int i = 0; i < 4; i++)
                wmma::load_matrix_sync(af[i],
                    a_s + (size_t)(wm * 64 + i * 16) * A_LD_H + ks * 16, A_LD_H);
            #pragma unroll
            for (int j = 0; j < 4; j++) {
                wmma::fragment<wmma::matrix_b, 16, 16, 16, __half, wmma::row_major> bfrag;
                wmma::load_matrix_sync(bfrag,
                    b_s + (size_t)(ks * 16) * B_LD_H + wn * 64 + j * 16, B_LD_H);
                #pragma unroll
                for (int i = 0; i < 4; i++)
                    wmma::mma_sync(cf[i][j], af[i], bfrag, cf[i][j]);
            }
        }

        if (gc + 1 < GTOT) CP_WAIT(0);
        __syncthreads();
        if (gc + 2 < GTOT) {
            load_b(gc + 2, sb + B0_OFF + (gc & 1) * B_SLOT_B, tid);
            CP_COMMIT();
        }

        if ((gc & 7) == 7) {
            int bb, tx; tile_of(gc, bx, bb, tx);
            pd_s[tid] = g_proj_dec[bb * ATTN + tid];

            const int row = tid >> 1, h = tid & 1;
            float e = 0.f;
            #pragma unroll
            for (int p = 0; p < 2; p++) {
                __syncthreads();
                if ((wn >> 1) == p) {
                    #pragma unroll
                    for (int i = 0; i < 4; i++)
                        #pragma unroll
                        for (int j = 0; j < 4; j++)
                            wmma::store_matrix_sync(
                                c2_s + (size_t)(wm * 64 + i * 16) * C_LD2
                                     + (wn & 1) * 64 + j * 16,
                                cf[i][j], C_LD2, wmma::mem_row_major);
                }
                __syncthreads();
                const float* crow = c2_s + (size_t)row * C_LD2 + h * 64;
                const float* pdq  = pd_s + p * 128 + h * 64;
                const float* vq   = v_s + p * 128 + h * 64;
                #pragma unroll 8
                for (int j = 0; j < 64; j++)
                    e = fmaf(fast_tanh(crow[j] + pdq[j]), vq[j], e);
            }
            e += __shfl_xor_sync(0xffffffffu, e, 1);
            if (h == 0)
                g_energy[bb * T + tx * TILE_M + row] = e;

            #pragma unroll
            for (int i = 0; i < 4; i++)
                #pragma unroll
                for (int j = 0; j < 4; j++)
                    wmma::fill_fragment(cf[i][j], 0.0f);
            __syncthreads();
        }
    }
}

// ---------------------------------------------------------------------------
// Fused softmax + context partials: grid (B, CSEG), block 128.
// Context partial accumulated straight into out_ctx via atomicAdd (REDG).
// ---------------------------------------------------------------------------
__global__ void __launch_bounds__(128)
ctx_softmax_kernel(const void* __restrict__ mask,
                   float* __restrict__ attn_out,
                   float* __restrict__ out_ctx) {
    __shared__ float sred[8];
    __shared__ float sw[CT];

    const int b   = blockIdx.x;
    const int seg = blockIdx.y;
    const int tb  = seg * CT;
    const int tid = threadIdx.x;

    const bool isbyte = (g_mask_is_byte != 0);
    const unsigned char* mb = (const unsigned char*)mask;
    const int*           mi = (const int*)mask;

    float e[16];
    #pragma unroll
    for (int j = 0; j < 16; j++) {
        const int i = b * T + tid + j * 128;
        const bool m = isbyte ? (mb[i] != 0) : (mi[i] != 0);
        e[j] = m ? -INFINITY : g_energy[i];
    }
    float mx = e[0];
    #pragma unroll
    for (int j = 1; j < 16; j++) mx = fmaxf(mx, e[j]);
    #pragma unroll
    for (int o = 16; o > 0; o >>= 1)
        mx = fmaxf(mx, __shfl_xor_sync(0xffffffffu, mx, o));
    if ((tid & 31) == 0) sred[tid >> 5] = mx;
    __syncthreads();
    if (tid < 32) {
        float t = (tid < 4) ? sred[tid] : -INFINITY;
        #pragma unroll
        for (int o = 2; o > 0; o >>= 1)
            t = fmaxf(t, __shfl_xor_sync(0xffffffffu, t, o));
        if (tid == 0) sred[4] = t;
    }
    __syncthreads();
    mx = sred[4];

    const bool allmasked = !(mx > -INFINITY);

    float s = 0.f;
    #pragma unroll
    for (int j = 0; j < 16; j++)
        s += (allmasked || e[j] == -INFINITY) ? 0.f : expf(e[j] - mx);
    #pragma unroll
    for (int o = 16; o > 0; o >>= 1)
        s += __shfl_xor_sync(0xffffffffu, s, o);
    __syncthreads();
    if ((tid & 31) == 0) sred[tid >> 5] = s;
    __syncthreads();
    if (tid < 32) {
        float t = (tid < 4) ? sred[tid] : 0.f;
        #pragma unroll
        for (int o = 2; o > 0; o >>= 1)
            t += __shfl_xor_sync(0xffffffffu, t, o);
        if (tid == 0) sred[5] = t;
    }
    __syncthreads();
    s = sred[5];
    const float inv = (s > 0.f) ? (1.f / s) : 0.f;

    if (tid < CT) {
        const int i = b * T + tb + tid;
        const bool m = isbyte ? (mb[i] != 0) : (mi[i] != 0);
        const float ev = (allmasked || m) ? -INFINITY : g_energy[i];
        const float w = (ev == -INFINITY) ? 0.f : expf(ev - mx) * inv;
        sw[tid] = w;
        attn_out[i] = w;
    }
    __syncthreads();

    const uint2* ep = (const uint2*)(g_enc_h + ((size_t)b * T + tb) * ENC) + tid;
    float4 acc = {0.f, 0.f, 0.f, 0.f};
    #pragma unroll 8
    for (int t = 0; t < CT; t++) {
        union { uint2 u; __half2 h[2]; } w;
        w.u = ep[(size_t)t * (ENC / 4)];
        const float sc = sw[t];
        float2 f0 = __half22float2(w.h[0]);
        float2 f1 = __half22float2(w.h[1]);
        acc.x = fmaf(sc, f0.x, acc.x);
        acc.y = fmaf(sc, f0.y, acc.y);
        acc.z = fmaf(sc, f1.x, acc.z);
        acc.w = fmaf(sc, f1.y, acc.w);
    }
    float* dst = out_ctx + b * ENC + tid * 4;
    atomicAdd(dst + 0, acc.x);
    atomicAdd(dst + 1, acc.y);
    atomicAdd(dst + 2, acc.z);
    atomicAdd(dst + 3, acc.w);
}

// ---------------------------------------------------------------------------
extern "C" void kernel_launch(void* const* d_in, const int* in_sizes, int n_in,
                              void* d_out, int out_size) {
    const float* enc  = (const float*)d_in[0];
    const float* dec  = (const float*)d_in[1];
    const void*  mask = d_in[2];
    const float* We   = (const float*)d_in[3];
    const float* Wd   = (const float*)d_in[4];
    const float* v    = (const float*)d_in[5];

    float* out_ctx  = (float*)d_out;
    float* out_attn = out_ctx + B * ENC;

    cudaFuncSetAttribute(energy_wmma_kernel,
                         cudaFuncAttributeMaxDynamicSharedMemorySize, DYN_SMEM);

    prep_kernel<<<290, 256>>>(dec, Wd, We, (const unsigned char*)mask, out_ctx);
    energy_wmma_kernel<<<EGRID, 256, DYN_SMEM>>>(enc, v);
    ctx_softmax_kernel<<<dim3(B, CSEG), 128>>>(mask, out_attn, out_ctx);
}